// round 17
// baseline (speedup 1.0000x reference)
#include <cuda_runtime.h>
#include <cstdint>

#define NROWS 8192
#define DDIM  8192
#define KIN   1024
#define NT    128      // two independent 64-thread row-groups
#define GRID  (NROWS / 2)

typedef unsigned long long ull;

// ---- packed f32x2 helpers (Blackwell sm_103a) ----
__device__ __forceinline__ ull pack2(float lo, float hi) {
    ull r; asm("mov.b64 %0, {%1, %2};" : "=l"(r) : "f"(lo), "f"(hi)); return r;
}
__device__ __forceinline__ void unpack2(ull v, float& lo, float& hi) {
    asm("mov.b64 {%0, %1}, %2;" : "=f"(lo), "=f"(hi) : "l"(v));
}
__device__ __forceinline__ ull f2add(ull a, ull b) {
    ull r; asm("add.rn.f32x2 %0, %1, %2;" : "=l"(r) : "l"(a), "l"(b)); return r;
}
// a - b == fma(b, -1, a)
__device__ __forceinline__ ull f2sub(ull a, ull b) {
    const ull NEG1 = 0xBF800000BF800000ULL;
    ull r; asm("fma.rn.f32x2 %0, %1, %2, %3;" : "=l"(r) : "l"(b), "l"(NEG1), "l"(a)); return r;
}
__device__ __forceinline__ ull f2mul(ull a, ull b) {
    ull r; asm("mul.rn.f32x2 %0, %1, %2;" : "=l"(r) : "l"(a), "l"(b)); return r;
}

// Storage swizzle: slot(e) = e ^ (((e>>7)&31)<<2)  (perturbs bits 2..6 only)
__device__ __forceinline__ int slot(int e) {
    return e ^ (((e >> 7) & 31) << 2);
}

// Named barrier over one 64-thread row-group (ids 1 and 2)
__device__ __forceinline__ void rowbar(int id) {
    asm volatile("bar.sync %0, 64;" :: "r"(id) : "memory");
}

__global__ void __launch_bounds__(NT, 3) fwht_kernel(
    const float* __restrict__ u, const int* __restrict__ idx, float* __restrict__ out)
{
    extern __shared__ float smraw[];            // 64 KB: two 32 KB row buffers
    const int t   = threadIdx.x;                // 0..127
    const int pr  = t >> 6;                     // row-group 0/1
    const int tl  = t & 63;                     // thread id within row-group
    const int bid = pr + 1;                     // named barrier id

    float*  sm  = smraw + pr * DDIM;
    float4* smv = reinterpret_cast<float4*>(sm);

    const int row = 2 * blockIdx.x + pr;
    const float* urow = u + (long)row * KIN;

    // ---- early global loads (16 keys + 16 values per thread) ----
    int4   iv[4];
    float4 uv[4];
    {
        const int4*   idx4 = reinterpret_cast<const int4*>(idx);
        const float4* u4   = reinterpret_cast<const float4*>(urow);
#pragma unroll
        for (int i = 0; i < 4; i++) { iv[i] = idx4[4 * tl + i]; uv[i] = u4[4 * tl + i]; }
    }
    int prev = (tl == 0) ? -1 : idx[16 * tl - 1];

    // ---- zero this row's 32KB half (STS.128, conflict-free) ----
    const float4 z4 = make_float4(0.f, 0.f, 0.f, 0.f);
#pragma unroll
    for (int i = 0; i < DDIM / 4 / 64; i++) smv[tl + 64 * i] = z4;
    rowbar(bid);

    // ---- scatter: idx SORTED -> run-leader plain stores (no atomics) ----
    {
        int   id[16]; float uu[16];
#pragma unroll
        for (int i = 0; i < 4; i++) {
            id[4*i] = iv[i].x; id[4*i+1] = iv[i].y; id[4*i+2] = iv[i].z; id[4*i+3] = iv[i].w;
            uu[4*i] = uv[i].x; uu[4*i+1] = uv[i].y; uu[4*i+2] = uv[i].z; uu[4*i+3] = uv[i].w;
        }
#pragma unroll
        for (int p = 0; p < 16; p++) {
            if (id[p] != prev) {
                float val = uu[p];
                int q = p + 1;
                while (q < 16 && id[q] == id[p]) { val += uu[q]; q++; }
                if (q == 16) {
                    int j = 16 * tl + 16;   // run spills past this thread's keys (rare)
                    while (j < KIN && idx[j] == id[p]) { val += urow[j]; j++; }
                }
                sm[slot(id[p])] = val;
            }
            prev = id[p];
        }
    }
    rowbar(bid);

    // ==== Phase 1: thread owns e in [128tl, 128tl+128); bits 0..6 in registers ====
    // e-quad c stored at slot-quad 32tl + (c ^ (tl&31))  -> 32x LDS.128 conflict-free
    {
        ull y[64];
        const int tm = tl & 31;
        const int qb = tl << 5;
#pragma unroll
        for (int c = 0; c < 32; c++) {
            float4 q = smv[qb + (c ^ tm)];
            y[2 * c]     = pack2(q.x + q.y, q.x - q.y);   // fold bit 0
            y[2 * c + 1] = pack2(q.z + q.w, q.z - q.w);
        }
        // bits 1..6: 6 packed stages over pair-index p = 0..63
#pragma unroll
        for (int m = 32; m >= 1; m >>= 1) {
#pragma unroll
            for (int j = 0; j < 64; j++) {
                if (!(j & m)) {
                    ull a = y[j], b = y[j | m];
                    y[j]     = f2add(a, b);
                    y[j | m] = f2sub(a, b);
                }
            }
        }
        // write back IN-PLACE (thread-exclusive slots, same addresses)
#pragma unroll
        for (int c = 0; c < 32; c++) {
            float a0, a1, b0, b1;
            unpack2(y[2 * c], a0, a1);
            unpack2(y[2 * c + 1], b0, b1);
            smv[qb + (c ^ tm)] = make_float4(a0, a1, b0, b1);
        }
    }
    rowbar(bid);   // P2 reads cross-thread (within row-group)

    // ==== Phase 2: bits 7..12; thread handles tau pair (2tl, 2tl+1), single pass ====
    // read e = tau + 128m at slot = 128m + (tau ^ ((m&31)<<2)); tau pair adjacent -> LDS.64
    {
        ull z[64];
        const int t2 = 2 * tl;
#pragma unroll
        for (int m = 0; m < 64; m++) {
            float2 v = *reinterpret_cast<const float2*>(
                &sm[128 * m + (t2 ^ ((m & 31) << 2))]);
            z[m] = pack2(v.x, v.y);   // packed lanes = (tau0, tau1)
        }
        // 6 packed stages over m (bits 7..12)
#pragma unroll
        for (int mm = 32; mm >= 1; mm >>= 1) {
#pragma unroll
            for (int j = 0; j < 64; j++) {
                if (!(j & mm)) {
                    ull a = z[j], b = z[j | mm];
                    z[j]      = f2add(a, b);
                    z[j | mm] = f2sub(a, b);
                }
            }
        }
        // scale + store: float2 at orow[128m + 2tl]  -> STG.64, coalesced
        const float SCALE = 0.011048543456039806f;  // 1/sqrt(8192)
        const ull SC2 = pack2(SCALE, SCALE);
        float2* orow2 = reinterpret_cast<float2*>(out + (long)row * DDIM);
#pragma unroll
        for (int m = 0; m < 64; m++) {
            float lo, hi;
            unpack2(f2mul(z[m], SC2), lo, hi);
            orow2[64 * m + tl] = make_float2(lo, hi);
        }
    }
}

extern "C" void kernel_launch(void* const* d_in, const int* in_sizes, int n_in,
                              void* d_out, int out_size)
{
    const float* u   = (const float*)d_in[0];
    const int*   idx = (const int*)d_in[1];
    float*       out = (float*)d_out;

    const int smem_bytes = 2 * DDIM * (int)sizeof(float);   // 64 KB
    cudaFuncSetAttribute(fwht_kernel,
                         cudaFuncAttributeMaxDynamicSharedMemorySize, smem_bytes);
    fwht_kernel<<<GRID, NT, smem_bytes>>>(u, idx, out);
}